// round 2
// baseline (speedup 1.0000x reference)
#include <cuda_runtime.h>
#include <cstdint>
#include <cstddef>

// Problem constants
#define TT   512     // timesteps
#define BSZ  64      // batch
#define IC_  512     // input channels
#define HC_  512     // hidden channels
#define ZC_  2048    // 4*HC
#define MR   (TT*BSZ)

// Recurrent kernel config
#define RK_CTAS 128
#define RK_THR  128
#define KCH     32   // k-chunk staged into smem per iteration

// ---------------------------------------------------------------------------
// Scratch (static device allocations — no cudaMalloc allowed)
// ---------------------------------------------------------------------------
__device__ float g_z[(size_t)MR * ZC_];        // 256 MB: precomputed x-projection (+bias)
__device__ float g_hseq[(size_t)MR * HC_];     // 64 MB: layer-0 h sequence
__device__ float g_hbuf[2][BSZ * HC_];         // double-buffered current h
__device__ unsigned g_barcnt = 0;
__device__ volatile unsigned g_bargen = 0;

// ---------------------------------------------------------------------------
// Helpers
// ---------------------------------------------------------------------------
__device__ __forceinline__ float sigf(float x) {
    return 1.0f / (1.0f + __expf(-x));
}
__device__ __forceinline__ float tanh_fast(float x) {
    float ax = fabsf(x);
    float e = __expf(-2.0f * ax);
    float r = (1.0f - e) / (1.0f + e);
    return copysignf(r, x);
}

// Software grid barrier (all RK_CTAS CTAs co-resident: grid=128 <= 148 SMs)
__device__ __forceinline__ void gbar() {
    __syncthreads();
    if (threadIdx.x == 0) {
        unsigned gen = g_bargen;
        __threadfence();
        if (atomicAdd(&g_barcnt, 1u) == RK_CTAS - 1) {
            g_barcnt = 0;
            __threadfence();
            g_bargen = gen + 1;
        } else {
            while (g_bargen == gen) { __nanosleep(32); }
            __threadfence();
        }
    }
    __syncthreads();
}

// ---------------------------------------------------------------------------
// Phase 1: Z = A @ W[0:512,:] + bias   (A: [32768,512] rm, W row-major stride 2048)
// Tiled fp32 SGEMM: 128x64 CTA tile, BK=16, 256 threads, 8x4 per-thread tile.
// Writes g_z.
// ---------------------------------------------------------------------------
__global__ __launch_bounds__(256) void sgemm_bias(
        const float* __restrict__ A,
        const float* __restrict__ W,
        const float* __restrict__ bias) {
    __shared__ float As[16][132];   // A tile, transposed, padded
    __shared__ float Bs[16][64];

    const int tid = threadIdx.x;
    const int m0 = blockIdx.y * 128;
    const int n0 = blockIdx.x * 64;
    const int ty = tid >> 4;          // 0..15 -> 8 rows each
    const int tx = tid & 15;          // 0..15 -> 4 cols each

    float acc[8][4];
#pragma unroll
    for (int i = 0; i < 8; i++) {
        acc[i][0] = 0.f; acc[i][1] = 0.f; acc[i][2] = 0.f; acc[i][3] = 0.f;
    }

    const int ar = tid >> 2;          // 0..63
    const int ac = (tid & 3) << 2;    // 0,4,8,12
    const int br = tid >> 4;          // 0..15
    const int bc = (tid & 15) << 2;   // 0..60

    for (int k0 = 0; k0 < 512; k0 += 16) {
#pragma unroll
        for (int rr = 0; rr < 2; rr++) {
            float4 v = *(const float4*)(A + (size_t)(m0 + ar + rr * 64) * 512 + k0 + ac);
            As[ac + 0][ar + rr * 64] = v.x;
            As[ac + 1][ar + rr * 64] = v.y;
            As[ac + 2][ar + rr * 64] = v.z;
            As[ac + 3][ar + rr * 64] = v.w;
        }
        *(float4*)&Bs[br][bc] = *(const float4*)(W + (size_t)(k0 + br) * ZC_ + n0 + bc);
        __syncthreads();
#pragma unroll
        for (int kk = 0; kk < 16; kk++) {
            float4 bv = *(float4*)&Bs[kk][tx << 2];
            float a0[8];
#pragma unroll
            for (int i = 0; i < 8; i++) a0[i] = As[kk][(ty << 3) + i];
#pragma unroll
            for (int i = 0; i < 8; i++) {
                acc[i][0] += a0[i] * bv.x;
                acc[i][1] += a0[i] * bv.y;
                acc[i][2] += a0[i] * bv.z;
                acc[i][3] += a0[i] * bv.w;
            }
        }
        __syncthreads();
    }

    float4 bb = *(const float4*)(bias + n0 + (tx << 2));
#pragma unroll
    for (int i = 0; i < 8; i++) {
        float4 o;
        o.x = acc[i][0] + bb.x;
        o.y = acc[i][1] + bb.y;
        o.z = acc[i][2] + bb.z;
        o.w = acc[i][3] + bb.w;
        *(float4*)(g_z + (size_t)(m0 + (ty << 3) + i) * ZC_ + n0 + (tx << 2)) = o;
    }
}

// ---------------------------------------------------------------------------
// Phase 2: persistent recurrent kernel for one layer.
// 128 CTAs x 128 threads. CTA cid owns h-columns [4*cid, 4*cid+4).
// Warp jj (0..3) handles h-column j0+jj; lane handles batch rows (lane, lane+32).
// Wh slice (512 x 16) resident in smem. h staged per 32-k chunk into smem
// transposed [k][b] with padding (conflict-free). c lives in registers.
// One global barrier per timestep (h double-buffered).
// ---------------------------------------------------------------------------
__global__ __launch_bounds__(RK_THR, 1) void lstm_rec(
        const float* __restrict__ Wh,     // [512, 2048] row-major (recurrent rows of W)
        const float* __restrict__ h0l,    // [512] initial h for this layer (broadcast over batch)
        const float* __restrict__ c0l,    // [512]
        float* __restrict__ hseq,         // [T*BS*HC] output h sequence
        float* __restrict__ hs_out,       // [BS*HC] final h
        float* __restrict__ cs_out) {     // [BS*HC] final c
    __shared__ float Wsm[512 * 16];            // 32 KB, layout [k][jj*4+g]
    __shared__ float Hs[KCH][BSZ + 1];         // staged h chunk, transposed + padded

    const int tid  = threadIdx.x;
    const int cid  = blockIdx.x;
    const int j0   = cid << 2;
    const int jj   = tid >> 5;
    const int lane = tid & 31;
    const int j    = j0 + jj;
    const int b0   = lane, b1 = lane + 32;

    // Load Wh slice: Wsm[k*16 + c], c = jj*4 + g  <-  Wh[k][g*512 + j0 + jj]
    for (int idx = tid; idx < 512 * 16; idx += RK_THR) {
        int k = idx >> 4, c = idx & 15;
        Wsm[idx] = Wh[(size_t)k * ZC_ + (size_t)(c & 3) * HC_ + j0 + (c >> 2)];
    }

    // Init h buffer (each thread owns its (b, j) cells; broadcast h0 over batch)
    float hv = h0l[j];
    g_hbuf[0][b0 * HC_ + j] = hv;
    g_hbuf[0][b1 * HC_ + j] = hv;
    float cA = c0l[j], cB = c0l[j];
    float hA = hv, hB = hv;
    __threadfence();
    gbar();

    int cur = 0;
    for (int t = 0; t < TT; t++) {
        const float* hb = g_hbuf[cur];

        // Init accumulators from precomputed x-projection (bias already folded in)
        float accA[4], accB[4];
        const float* zr0 = g_z + (size_t)(t * BSZ + b0) * ZC_ + j;
        const float* zr1 = g_z + (size_t)(t * BSZ + b1) * ZC_ + j;
#pragma unroll
        for (int g = 0; g < 4; g++) {
            accA[g] = zr0[(size_t)g * HC_];
            accB[g] = zr1[(size_t)g * HC_];
        }

        // Software-pipelined staging: prefetch chunk 0
        float4 pf[4];
#pragma unroll
        for (int i = 0; i < 4; i++) {
            int idx4 = tid + (i << 7);
            int kk4 = idx4 & 7, b = idx4 >> 3;
            pf[i] = *(const float4*)(hb + (size_t)b * HC_ + (kk4 << 2));
        }

#pragma unroll 1
        for (int c = 0; c < HC_ / KCH; c++) {
            __syncthreads();
#pragma unroll
            for (int i = 0; i < 4; i++) {
                int idx4 = tid + (i << 7);
                int kk4 = idx4 & 7, b = idx4 >> 3;
                Hs[(kk4 << 2) + 0][b] = pf[i].x;
                Hs[(kk4 << 2) + 1][b] = pf[i].y;
                Hs[(kk4 << 2) + 2][b] = pf[i].z;
                Hs[(kk4 << 2) + 3][b] = pf[i].w;
            }
            __syncthreads();
            if (c + 1 < HC_ / KCH) {
                int k0n = (c + 1) * KCH;
#pragma unroll
                for (int i = 0; i < 4; i++) {
                    int idx4 = tid + (i << 7);
                    int kk4 = idx4 & 7, b = idx4 >> 3;
                    pf[i] = *(const float4*)(hb + (size_t)b * HC_ + k0n + (kk4 << 2));
                }
            }
            const float* wrow = Wsm + (size_t)c * KCH * 16 + (jj << 2);
#pragma unroll
            for (int kk = 0; kk < KCH; kk++) {
                float4 w = *(const float4*)(wrow + kk * 16);   // broadcast within warp
                float ha  = Hs[kk][b0];
                float hbv = Hs[kk][b1];
                accA[0] += ha  * w.x;  accA[1] += ha  * w.y;
                accA[2] += ha  * w.z;  accA[3] += ha  * w.w;
                accB[0] += hbv * w.x;  accB[1] += hbv * w.y;
                accB[2] += hbv * w.z;  accB[3] += hbv * w.w;
            }
        }

        // Gates: z split order is (f, i, o, g); forget bias = 1.0
        float fA = sigf(accA[0] + 1.0f), iA = sigf(accA[1]), oA = sigf(accA[2]);
        float gA = tanh_fast(accA[3]);
        cA = cA * fA + gA * iA;
        hA = oA * tanh_fast(cA);

        float fB = sigf(accB[0] + 1.0f), iB = sigf(accB[1]), oB = sigf(accB[2]);
        float gB = tanh_fast(accB[3]);
        cB = cB * fB + gB * iB;
        hB = oB * tanh_fast(cB);

        int nxt = cur ^ 1;
        g_hbuf[nxt][b0 * HC_ + j] = hA;
        g_hbuf[nxt][b1 * HC_ + j] = hB;
        hseq[(size_t)(t * BSZ + b0) * HC_ + j] = hA;
        hseq[(size_t)(t * BSZ + b1) * HC_ + j] = hB;
        __threadfence();
        gbar();
        cur = nxt;
    }

    hs_out[b0 * HC_ + j] = hA;
    hs_out[b1 * HC_ + j] = hB;
    cs_out[b0 * HC_ + j] = cA;
    cs_out[b1 * HC_ + j] = cB;
}

// ---------------------------------------------------------------------------
// Launch: sgemm(L0) -> rec(L0) -> sgemm(L1, input = L0 h-seq) -> rec(L1 -> d_out)
// ---------------------------------------------------------------------------
extern "C" void kernel_launch(void* const* d_in, const int* in_sizes, int n_in,
                              void* d_out, int out_size) {
    const float* x  = (const float*)d_in[0];
    const float* W0 = (const float*)d_in[1];
    const float* b0 = (const float*)d_in[2];
    const float* W1 = (const float*)d_in[3];
    const float* b1 = (const float*)d_in[4];
    const float* h0 = (const float*)d_in[5];
    const float* c0 = (const float*)d_in[6];

    float* out = (float*)d_out;                      // [T, BS, HC]
    float* hs  = out + (size_t)TT * BSZ * HC_;       // [L, BS, HC]
    float* cs  = hs + (size_t)2 * BSZ * HC_;         // [L, BS, HC]

    float* hseq0 = nullptr;
    cudaGetSymbolAddress((void**)&hseq0, g_hseq);

    dim3 ggrid(ZC_ / 64, MR / 128);

    // Layer 0
    sgemm_bias<<<ggrid, 256>>>(x, W0, b0);
    lstm_rec<<<RK_CTAS, RK_THR>>>(W0 + (size_t)IC_ * ZC_, h0, c0,
                                  hseq0, hs, cs);
    // Layer 1
    sgemm_bias<<<ggrid, 256>>>(hseq0, W1, b1);
    lstm_rec<<<RK_CTAS, RK_THR>>>(W1 + (size_t)HC_ * ZC_, h0 + HC_, c0 + HC_,
                                  out, hs + BSZ * HC_, cs + BSZ * HC_);
}

// round 4
// speedup vs baseline: 1.3769x; 1.3769x over previous
#include <cuda_runtime.h>
#include <cstdint>
#include <cstddef>

// Problem constants
#define TT   512
#define BSZ  64
#define IC_  512
#define HC_  512
#define ZC_  2048
#define MR   (TT*BSZ)

#define RK_CTAS 128
#define RK_THR  256

typedef unsigned long long ull;

// ---------------------------------------------------------------------------
// Static device scratch (no cudaMalloc allowed)
// ---------------------------------------------------------------------------
__device__ float g_z[(size_t)MR * ZC_];        // 256 MB: x-projection (+bias), [m][2048]
__device__ float g_hseq[(size_t)MR * HC_];     // 64 MB: layer-0 h sequence [m][512]
__device__ float g_hbuf[2][HC_ * BSZ];         // double-buffered h, TRANSPOSED [j][b]
__device__ unsigned g_barcnt = 0;
__device__ volatile unsigned g_bargen = 0;

// ---------------------------------------------------------------------------
// f32x2 helpers (Blackwell packed fp32 FMA — SASS FFMA2)
// ---------------------------------------------------------------------------
__device__ __forceinline__ ull pack2(float x, float y) {
    ull r; asm("mov.b64 %0, {%1, %2};" : "=l"(r) : "f"(x), "f"(y)); return r;
}
__device__ __forceinline__ void unpack2(ull v, float& x, float& y) {
    asm("mov.b64 {%0, %1}, %2;" : "=f"(x), "=f"(y) : "l"(v));
}
__device__ __forceinline__ void ffma2(ull& d, ull a, ull b) {
    asm("fma.rn.f32x2 %0, %1, %2, %0;" : "+l"(d) : "l"(a), "l"(b));
}

__device__ __forceinline__ float sigf(float x) { return 1.0f / (1.0f + __expf(-x)); }
__device__ __forceinline__ float tanh_fast(float x) {
    float ax = fabsf(x);
    float e = __expf(-2.0f * ax);
    float r = (1.0f - e) / (1.0f + e);
    return copysignf(r, x);
}

// Software grid barrier: 128 CTAs co-resident.
__device__ __forceinline__ void gbar() {
    __syncthreads();
    if (threadIdx.x == 0) {
        __threadfence();
        unsigned gen = g_bargen;
        if (atomicAdd(&g_barcnt, 1u) == RK_CTAS - 1) {
            g_barcnt = 0;
            __threadfence();
            g_bargen = gen + 1;
        } else {
            while (g_bargen == gen) {}
        }
        __threadfence();
    }
    __syncthreads();
}

// ---------------------------------------------------------------------------
// Phase 1: Z = A @ W[0:512,:] + bias, fp32 via packed FFMA2.
// Tile M=128,N=128,BK=16, 256 threads, per-thread 8x8 (32 FFMA2).
// A staged DUPLICATED (a,a) so the inner loop has zero pack instructions.
// ---------------------------------------------------------------------------
#define AS_STRIDE 264   // floats per k-row (256 data + 8 pad), 16B-aligned rows
#define BS_STRIDE 136   // floats per k-row (128 data + 8 pad), 16B-aligned rows

__global__ __launch_bounds__(256) void sgemm_bias(
        const float* __restrict__ A,       // [32768, 512] row-major
        const float* __restrict__ W,       // [>=512, 2048] row-major (use rows 0..511)
        const float* __restrict__ bias,    // [2048]
        float* __restrict__ Z) {           // [32768, 2048]
    __shared__ float As2[16 * AS_STRIDE];  // 16.5 KB, dup'd A: [k][2m]
    __shared__ float Bs[16 * BS_STRIDE];   // 8.5 KB:          [k][n]

    const int tid = threadIdx.x;
    const int m0 = blockIdx.y * 128;
    const int n0 = blockIdx.x * 128;
    const int tx = tid & 15;        // n quad
    const int ty = tid >> 4;        // m quad

    ull acc[8][4];
#pragma unroll
    for (int i = 0; i < 8; i++)
#pragma unroll
        for (int j = 0; j < 4; j++) acc[i][j] = 0ull;

    const int ar = tid >> 2, ac4 = tid & 3;     // A loads
    const int br = tid >> 5, bc4 = tid & 31;    // B loads

    for (int k0 = 0; k0 < 512; k0 += 16) {
        // Stage A (duplicated) and B
#pragma unroll
        for (int p = 0; p < 2; p++) {
            int r = ar + p * 64;
            float4 v = *(const float4*)(A + (size_t)(m0 + r) * 512 + k0 + ac4 * 4);
            const float* vf = (const float*)&v;
#pragma unroll
            for (int q = 0; q < 4; q++) {
                As2[(ac4 * 4 + q) * AS_STRIDE + 2 * r]     = vf[q];
                As2[(ac4 * 4 + q) * AS_STRIDE + 2 * r + 1] = vf[q];
            }
        }
#pragma unroll
        for (int p = 0; p < 2; p++) {
            int rB = br + p * 8;
            *(float4*)&Bs[rB * BS_STRIDE + bc4 * 4] =
                *(const float4*)(W + (size_t)(k0 + rB) * ZC_ + n0 + bc4 * 4);
        }
        __syncthreads();

#pragma unroll
        for (int kk = 0; kk < 16; kk++) {
            ull a[8], b[4];
            {
                const ulonglong2* ap = (const ulonglong2*)&As2[kk * AS_STRIDE + 8 * ty];
                ulonglong2 a01 = ap[0], a23 = ap[1];
                a[0] = a01.x; a[1] = a01.y; a[2] = a23.x; a[3] = a23.y;
                const ulonglong2* ap2 = (const ulonglong2*)&As2[kk * AS_STRIDE + 128 + 8 * ty];
                ulonglong2 a45 = ap2[0], a67 = ap2[1];
                a[4] = a45.x; a[5] = a45.y; a[6] = a67.x; a[7] = a67.y;
            }
            {
                // First n-quad at float offset 4*tx (n = n0+4tx..+3),
                // second at 64 + 4*tx (n = n0+64+4tx..+3). Bs rows are 128
                // data floats wide (NOT duplicated).
                ulonglong2 b01 = *(const ulonglong2*)&Bs[kk * BS_STRIDE + 4 * tx];
                ulonglong2 b23 = *(const ulonglong2*)&Bs[kk * BS_STRIDE + 64 + 4 * tx];
                b[0] = b01.x; b[1] = b01.y; b[2] = b23.x; b[3] = b23.y;
            }
#pragma unroll
            for (int i = 0; i < 8; i++)
#pragma unroll
                for (int j = 0; j < 4; j++)
                    ffma2(acc[i][j], a[i], b[j]);
        }
        __syncthreads();
    }

    // Epilogue: coalesced STG.128, bias added
    float4 bv0 = *(const float4*)(bias + n0 + 4 * tx);
    float4 bv1 = *(const float4*)(bias + n0 + 64 + 4 * tx);
#pragma unroll
    for (int i = 0; i < 8; i++) {
        int m = m0 + ((i < 4) ? (ty * 4 + i) : (64 + ty * 4 + (i - 4)));
        float x0, x1, x2, x3;
        unpack2(acc[i][0], x0, x1);
        unpack2(acc[i][1], x2, x3);
        float4 o0 = make_float4(x0 + bv0.x, x1 + bv0.y, x2 + bv0.z, x3 + bv0.w);
        *(float4*)(Z + (size_t)m * ZC_ + n0 + 4 * tx) = o0;
        unpack2(acc[i][2], x0, x1);
        unpack2(acc[i][3], x2, x3);
        float4 o1 = make_float4(x0 + bv1.x, x1 + bv1.y, x2 + bv1.z, x3 + bv1.w);
        *(float4*)(Z + (size_t)m * ZC_ + n0 + 64 + 4 * tx) = o1;
    }
}

// ---------------------------------------------------------------------------
// Phase 2: persistent recurrence. 128 CTAs x 256 threads (8 warps).
// CTA owns 4 h-columns. Warp w: kq = w>>1 (k range of 128), bh = w&1 (batch half).
// Thread: 1 batch row, 4 cols x 2 gate-pairs = 8 f32x2 accumulators.
// Per kk: 1 coalesced LDG.cg (h), 1 pack, 4 broadcast LDS.128 (w pairs), 8 FFMA2.
// Cross-warp k-reduction via 16KB smem; gating spread over all 256 threads.
// ---------------------------------------------------------------------------
__global__ __launch_bounds__(RK_THR, 1) void lstm_rec(
        const float* __restrict__ Wh,     // [512, 2048] recurrent rows of W
        const float* __restrict__ h0l,    // [512]
        const float* __restrict__ c0l,    // [512]
        float* __restrict__ hseq,         // [T*BS*HC]
        float* __restrict__ hs_out,       // [BS*HC]
        float* __restrict__ cs_out) {     // [BS*HC]
    __shared__ float Wsm[HC_ * 16];       // 32 KB: [k][c*4+g]
    __shared__ ull  Rsm[8 * 4 * 64];      // 16 KB: [(idx*4+kq)*64 + b]

    const int tid  = threadIdx.x;
    const int cid  = blockIdx.x;
    const int j0   = cid << 2;
    const int wid  = tid >> 5, lane = tid & 31;
    const int kq   = wid >> 1, bh = wid & 1;
    const int kbase = kq << 7;
    const int bb   = (bh << 5) + lane;    // batch row for GEMM

    // Weights: Wsm[k*16 + c*4 + g] = Wh[k][g*512 + j0 + c]
    for (int idx = tid; idx < HC_ * 16; idx += RK_THR) {
        int k = idx >> 4, c = (idx >> 2) & 3, g = idx & 3;
        Wsm[idx] = Wh[(size_t)k * ZC_ + (size_t)g * HC_ + j0 + c];
    }

    // Finalizer identity: thread -> (col fc, batch fb)
    const int fc = tid >> 6;
    const int fb = tid & 63;
    const int fj = j0 + fc;
    float cstate = c0l[fj];
    float hlast  = h0l[fj];
    g_hbuf[0][fj * BSZ + fb] = hlast;
    gbar();

    int cur = 0;
    for (int t = 0; t < TT; t++) {
        // Prefetch this thread's z (issued early; consumed after reduction)
        const float* zr = g_z + (size_t)(t * BSZ + fb) * ZC_ + fj;
        float z0 = __ldcg(zr);
        float z1 = __ldcg(zr + HC_);
        float z2 = __ldcg(zr + 2 * HC_);
        float z3 = __ldcg(zr + 3 * HC_);

        const float* hb = g_hbuf[cur];
        ull acc[4][2];
#pragma unroll
        for (int c = 0; c < 4; c++) { acc[c][0] = 0ull; acc[c][1] = 0ull; }

#pragma unroll 8
        for (int kk = 0; kk < 128; kk++) {
            int k = kbase + kk;
            float hv = __ldcg(hb + k * BSZ + bb);
            ull h2 = pack2(hv, hv);
            const float* wrow = Wsm + k * 16;
#pragma unroll
            for (int c = 0; c < 4; c++) {
                ulonglong2 w2 = *(const ulonglong2*)(wrow + c * 4);
                ffma2(acc[c][0], h2, w2.x);
                ffma2(acc[c][1], h2, w2.y);
            }
        }

        // Store partials: Rsm[(idx*4 + kq)*64 + b], idx = c*2+p  (conflict-free)
#pragma unroll
        for (int c = 0; c < 4; c++)
#pragma unroll
            for (int p = 0; p < 2; p++)
                Rsm[((c * 2 + p) * 4 + kq) * 64 + bb] = acc[c][p];
        __syncthreads();

        // Finalize: reduce 4 kq partials for cell (fc, fb), gate, update state
        float f = z0, i = z1, o = z2, g = z3;
#pragma unroll
        for (int q = 0; q < 4; q++) {
            float a0, a1, a2, a3;
            unpack2(Rsm[((fc * 2 + 0) * 4 + q) * 64 + fb], a0, a1);
            unpack2(Rsm[((fc * 2 + 1) * 4 + q) * 64 + fb], a2, a3);
            f += a0; i += a1; o += a2; g += a3;
        }
        f = sigf(f + 1.0f);           // FORGET_BIAS
        i = sigf(i);
        o = sigf(o);
        g = tanh_fast(g);
        cstate = cstate * f + g * i;
        hlast = o * tanh_fast(cstate);

        int nxt = cur ^ 1;
        __stcg(&g_hbuf[nxt][fj * BSZ + fb], hlast);
        hseq[(size_t)(t * BSZ + fb) * HC_ + fj] = hlast;
        gbar();
        cur = nxt;
    }

    hs_out[fb * HC_ + fj] = hlast;
    cs_out[fb * HC_ + fj] = cstate;
}

// ---------------------------------------------------------------------------
// Launch: sgemm(L0) -> rec(L0) -> sgemm(L1) -> rec(L1 -> d_out)
// ---------------------------------------------------------------------------
extern "C" void kernel_launch(void* const* d_in, const int* in_sizes, int n_in,
                              void* d_out, int out_size) {
    const float* x  = (const float*)d_in[0];
    const float* W0 = (const float*)d_in[1];
    const float* b0 = (const float*)d_in[2];
    const float* W1 = (const float*)d_in[3];
    const float* b1 = (const float*)d_in[4];
    const float* h0 = (const float*)d_in[5];
    const float* c0 = (const float*)d_in[6];

    float* out = (float*)d_out;                      // [T, BS, HC]
    float* hs  = out + (size_t)TT * BSZ * HC_;       // [L, BS, HC]
    float* cs  = hs + (size_t)2 * BSZ * HC_;         // [L, BS, HC]

    float* zptr = nullptr;
    float* hseq0 = nullptr;
    cudaGetSymbolAddress((void**)&zptr, g_z);
    cudaGetSymbolAddress((void**)&hseq0, g_hseq);

    dim3 ggrid(ZC_ / 128, MR / 128);

    // Layer 0
    sgemm_bias<<<ggrid, 256>>>(x, W0, b0, zptr);
    lstm_rec<<<RK_CTAS, RK_THR>>>(W0 + (size_t)IC_ * ZC_, h0, c0,
                                  hseq0, hs, cs);
    // Layer 1
    sgemm_bias<<<ggrid, 256>>>(hseq0, W1, b1, zptr);
    lstm_rec<<<RK_CTAS, RK_THR>>>(W1 + (size_t)HC_ * ZC_, h0 + HC_, c0 + HC_,
                                  out, hs + BSZ * HC_, cs + BSZ * HC_);
}